// round 7
// baseline (speedup 1.0000x reference)
#include <cuda_runtime.h>
#include <cstdint>

// Problem constants (fixed by the reference: N=64, T=2048, F=256)
#define CBS_N 64
#define CBS_T 2048
#define CBS_F 256
#define CBS_F4 (CBS_F / 4)      // 64 float4 per (n, t) row
#define THREADS_PER_ROW 8        // each thread: 8 float4 (128B), stride 8
#define ROWS_PER_BLOCK (256 / THREADS_PER_ROW)   // 32

// History:
//  - R4: 1 float4/thread -> 26.6us bench; issue-bound (50.6%), DRAM 49.6%.
//  - R5: 4 consecutive float4/thread -> 39.3us; uncoalesced (L1 73%).
//  - R6: 4 interleaved float4/thread -> 24.6us kernel / 27.4us bench;
//    NOTHING saturated (DRAM 53, L1 55, issue 17) => latency/MLP-bound.
//  - R7 (this): 8 interleaved float4/thread (128B, MLP=8) to push more
//    outstanding bytes per warp at the HBM controllers.

__device__ __forceinline__ int imax_(int a, int b) { return a > b ? a : b; }
__device__ __forceinline__ int imin_(int a, int b) { return a < b ? a : b; }

// grid = (T/32, N) = (64, 64), block = 256.
__global__ void chunk_by_slices_v4_kernel(const float4* __restrict__ x,
                                          const int* __restrict__ slices,
                                          const int* __restrict__ lens,
                                          float4* __restrict__ out,
                                          float* __restrict__ out_lens) {
    const int n = blockIdx.y;

    // Per-row parameters; uniform across the block -> L1 broadcast.
    const int s = slices[2 * n];
    const int e = slices[2 * n + 1];
    const int chunk_len = imax_(e - s, 0);
    const int left_pad  = (chunk_len == 0) ? 0 : imax_(-s, 0);
    const int start_    = imax_(s, 0);
    const int end_      = imin_(e, lens[n]);
    const int slice_len = imax_(end_ - start_, 0);

    // Fused chunk_lens write: one thread per n.
    if (blockIdx.x == 0 && threadIdx.x == 0) {
        out_lens[n] = (float)chunk_len;
    }

    const int t  = blockIdx.x * ROWS_PER_BLOCK + (threadIdx.x >> 3);
    const int f0 = threadIdx.x & 7;   // f = f0 + 8k, k = 0..7

    const bool valid = (t >= left_pad) && (t < left_pad + slice_len);

    int src = start_ + t - left_pad;
    src = imin_(imax_(src, 0), CBS_T - 1);

    float4 v[8];
    if (valid) {
        const float4* xr = &x[(n * CBS_T + src) * CBS_F4 + f0];
        #pragma unroll
        for (int k = 0; k < 8; k++) v[k] = __ldg(xr + 8 * k);
    } else {
        #pragma unroll
        for (int k = 0; k < 8; k++) v[k] = make_float4(0.f, 0.f, 0.f, 0.f);
    }

    float4* op = &out[(n * CBS_T + t) * CBS_F4 + f0];
    #pragma unroll
    for (int k = 0; k < 8; k++) __stcs(op + 8 * k, v[k]);
}

extern "C" void kernel_launch(void* const* d_in, const int* in_sizes, int n_in,
                              void* d_out, int out_size) {
    const float4* x      = (const float4*)d_in[0];
    const int*    slices = (const int*)d_in[1];
    const int*    lens   = (const int*)d_in[2];
    float4*       out    = (float4*)d_out;

    const long long chunks_elems = (long long)CBS_N * CBS_T * CBS_F;
    float* out_lens = ((float*)d_out) + chunks_elems;

    dim3 block(256);
    dim3 grid(CBS_T / ROWS_PER_BLOCK, CBS_N);  // (64, 64)
    chunk_by_slices_v4_kernel<<<grid, block>>>(x, slices, lens, out, out_lens);
}